// round 13
// baseline (speedup 1.0000x reference)
#include <cuda_runtime.h>
#include <cuda_bf16.h>
#include <math.h>

#define B_     4096
#define E_     64
#define D_     1024

// ---------------- scratch (__device__ globals; no allocs allowed) ----------
__device__ __align__(16) float         g_sinv[D_];
__device__ __align__(16) __nv_bfloat16 g_esb[E_ * D_];    // bf16 sinv*ek, [e][d]
__device__ __align__(16) __nv_bfloat16 g_ekTb[D_ * E_];   // bf16 ek^T, [d][e]
__device__ __align__(16) __nv_bfloat16 g_wres[B_ * E_];   // bf16 (w - 1/64)
__device__ __align__(16) float         g_en[E_];
__device__ __align__(16) float         g_mean[D_];        // (1/64)*colsum(ek)

// ---------------- mma.sync helpers (base ISA, compute_103-safe) ------------
static __device__ __forceinline__ void ldsm_x4(unsigned& r0, unsigned& r1,
                                               unsigned& r2, unsigned& r3,
                                               unsigned addr) {
    asm volatile("ldmatrix.sync.aligned.m8n8.x4.shared.b16 {%0,%1,%2,%3}, [%4];"
                 : "=r"(r0), "=r"(r1), "=r"(r2), "=r"(r3) : "r"(addr));
}
static __device__ __forceinline__ void mma_bf16(float& c0, float& c1,
                                                float& c2, float& c3,
                                                unsigned a0, unsigned a1,
                                                unsigned a2, unsigned a3,
                                                unsigned b0, unsigned b1) {
    asm volatile(
        "mma.sync.aligned.m16n8k16.row.col.f32.bf16.bf16.f32 "
        "{%0,%1,%2,%3}, {%4,%5,%6,%7}, {%8,%9}, {%0,%1,%2,%3};"
        : "+f"(c0), "+f"(c1), "+f"(c2), "+f"(c3)
        : "r"(a0), "r"(a1), "r"(a2), "r"(a3), "r"(b0), "r"(b1));
}

#define PAD 72   // 144 B row stride -> 4-bank skew, conflict-free ldmatrix

// ---------------------------------------------------------------------------
// prep: sigma_inv, es->bf16 (row-major), ek^T->bf16, expert norms
// ---------------------------------------------------------------------------
__global__ __launch_bounds__(256) void prep_kernel(const float* __restrict__ ek,
                                                   const float* __restrict__ ls) {
    int e = blockIdx.x;
    int tid = threadIdx.x;
    float acc = 0.f;
    for (int d = tid; d < D_; d += 256) {
        float s = __expf(-ls[d]);
        if (e == 0) g_sinv[d] = s;
        float v = ek[e * D_ + d];
        float sv = s * v;
        g_esb[e * D_ + d] = __float2bfloat16(sv);
        g_ekTb[d * E_ + e] = __float2bfloat16(v);
        acc += sv * v;
    }
    __shared__ float red[8];
    #pragma unroll
    for (int o = 16; o > 0; o >>= 1) acc += __shfl_down_sync(0xffffffffu, acc, o);
    if ((tid & 31) == 0) red[tid >> 5] = acc;
    __syncthreads();
    if (tid == 0) {
        float s = 0.f;
        #pragma unroll
        for (int i = 0; i < 8; i++) s += red[i];
        g_en[e] = s;
    }
}

// ---------------------------------------------------------------------------
// meank: g_mean[d] = (1/64) * sum_e ek[e][d]
// ---------------------------------------------------------------------------
__global__ __launch_bounds__(256) void meank(const float* __restrict__ ek) {
    int d = blockIdx.x * 256 + threadIdx.x;
    float acc = 0.f;
    #pragma unroll 8
    for (int e = 0; e < E_; e++) acc += ek[(size_t)e * D_ + d];
    g_mean[d] = acc * 0.015625f;
}

// ---------------------------------------------------------------------------
// kA: FUSED dist GEMM + similarity + softmax + residual weights.
// grid B/64 = 64 CTAs, 128 threads (4 warps). CTA: 64m x 64e x K=1024.
// Stages z fp32 -> bf16 (computing zn inline), full-K accumulation in regs,
// softmax in accumulator fragments. Double-buffered smem + reg prefetch.
// Static smem: 2*9216*2 + 4096 + 256 + 256 = 41472 B (< 48 KB).
// ---------------------------------------------------------------------------
__global__ __launch_bounds__(128) void kA_dist(const float* __restrict__ z,
                                               float* __restrict__ out_sim) {
    __shared__ __align__(16) __nv_bfloat16 sA[2][64 * PAD];
    __shared__ __align__(16) __nv_bfloat16 sB[2][64 * PAD];
    __shared__ __align__(16) float s_sinv[D_];
    __shared__ __align__(16) float s_en[E_];
    __shared__ float s_zn[64];

    const int tid = threadIdx.x;
    const int wid = tid >> 5, lane = tid & 31;
    const int r0 = blockIdx.x * 64;

    for (int i = tid; i < D_ / 4; i += 128)
        ((float4*)s_sinv)[i] = ((const float4*)g_sinv)[i];
    if (tid < E_ / 4) ((float4*)s_en)[tid] = ((const float4*)g_en)[tid];
    __syncthreads();

    const int r = tid >> 1, h = tid & 1;           // 2 threads per row
    const float* zrow = z + (size_t)(r0 + r) * D_ + h * 32;
    const __nv_bfloat16* erow = g_esb + (size_t)r * D_ + h * 32;

    float4 za[8];
    uint4  eb[4];
    {   // prefetch chunk 0
        const float4* zs = (const float4*)zrow;
        #pragma unroll
        for (int u = 0; u < 8; u++) za[u] = zs[u];
        const uint4* es = (const uint4*)erow;
        #pragma unroll
        for (int u = 0; u < 4; u++) eb[u] = es[u];
    }

    const int l7 = lane & 7;
    const int aRow = wid * 16 + l7 + ((lane >> 3) & 1) * 8;
    const int aKo  = (lane >> 4) * 8;
    const int bNo  = l7 + (lane >> 4) * 8;
    const int bKo  = ((lane >> 3) & 1) * 8;

    float acc[8][4];
    #pragma unroll
    for (int j = 0; j < 8; j++)
        #pragma unroll
        for (int q = 0; q < 4; q++) acc[j][q] = 0.f;
    float zn = 0.f;

    for (int c = 0; c < 16; c++) {
        const int p = c & 1;
        {   // store prefetched regs -> smem buf p; accumulate zn from fp32
            const int base = h * 32;
            const float* sv = s_sinv + c * 64 + base;
            #pragma unroll
            for (int u = 0; u < 8; u++) {
                float4 f = za[u];
                float4 s = *(const float4*)(sv + 4 * u);
                zn += s.x * f.x * f.x + s.y * f.y * f.y
                    + s.z * f.z * f.z + s.w * f.w * f.w;
                __nv_bfloat162 b01 = __floats2bfloat162_rn(f.x, f.y);
                __nv_bfloat162 b23 = __floats2bfloat162_rn(f.z, f.w);
                uint2 pk;
                pk.x = *reinterpret_cast<unsigned*>(&b01);
                pk.y = *reinterpret_cast<unsigned*>(&b23);
                *(uint2*)(&sA[p][r * PAD + base + 4 * u]) = pk;
            }
            #pragma unroll
            for (int u = 0; u < 4; u++)
                *(uint4*)(&sB[p][r * PAD + base + 8 * u]) = eb[u];
        }
        __syncthreads();
        if (c < 15) {   // prefetch chunk c+1 (overlaps with MMA below)
            const float4* zs = (const float4*)(zrow + (c + 1) * 64);
            #pragma unroll
            for (int u = 0; u < 8; u++) za[u] = zs[u];
            const uint4* es = (const uint4*)(erow + (c + 1) * 64);
            #pragma unroll
            for (int u = 0; u < 4; u++) eb[u] = es[u];
        }
        const unsigned sA_addr = (unsigned)__cvta_generic_to_shared(&sA[p][0]);
        const unsigned sB_addr = (unsigned)__cvta_generic_to_shared(&sB[p][0]);
        #pragma unroll
        for (int k16 = 0; k16 < 4; k16++) {
            const int k0 = k16 * 16;
            unsigned a0, a1, a2, a3;
            ldsm_x4(a0, a1, a2, a3, sA_addr + (aRow * PAD + k0 + aKo) * 2);
            #pragma unroll
            for (int g = 0; g < 4; g++) {
                unsigned b0, b1, b2, b3;
                ldsm_x4(b0, b1, b2, b3,
                        sB_addr + ((16 * g + bNo) * PAD + k0 + bKo) * 2);
                mma_bf16(acc[2*g][0], acc[2*g][1], acc[2*g][2], acc[2*g][3],
                         a0, a1, a2, a3, b0, b1);
                mma_bf16(acc[2*g+1][0], acc[2*g+1][1], acc[2*g+1][2], acc[2*g+1][3],
                         a0, a1, a2, a3, b2, b3);
            }
        }
    }

    // finalize zn (2 threads per row are adjacent lanes)
    zn += __shfl_xor_sync(0xffffffffu, zn, 1);
    if (h == 0) s_zn[r] = zn;
    __syncthreads();

    // epilogue: similarity + softmax inside accumulator fragments
    const int gr = lane >> 2, tc = (lane & 3) * 2;
    const int raL = wid * 16 + gr, rbL = raL + 8;
    const float zna = s_zn[raL], znb = s_zn[rbL];

    float sa[16], sb[16];
    float mxa = -1e30f, mxb = -1e30f;
    #pragma unroll
    for (int j = 0; j < 8; j++) {
        #pragma unroll
        for (int t = 0; t < 2; t++) {
            const int n = 8 * j + tc + t;
            const float en = s_en[n];
            float va = 1.f / (1.f + zna + en - 2.f * acc[j][t]);
            float vb = 1.f / (1.f + znb + en - 2.f * acc[j][2 + t]);
            sa[2 * j + t] = va; sb[2 * j + t] = vb;
            mxa = fmaxf(mxa, va); mxb = fmaxf(mxb, vb);
        }
        *(float2*)(out_sim + (size_t)(r0 + raL) * E_ + 8 * j + tc)
            = make_float2(sa[2 * j], sa[2 * j + 1]);
        *(float2*)(out_sim + (size_t)(r0 + rbL) * E_ + 8 * j + tc)
            = make_float2(sb[2 * j], sb[2 * j + 1]);
    }
    // quad all-reduce (lanes 4g..4g+3 own one row's 64 values)
    mxa = fmaxf(mxa, __shfl_xor_sync(0xffffffffu, mxa, 1));
    mxa = fmaxf(mxa, __shfl_xor_sync(0xffffffffu, mxa, 2));
    mxb = fmaxf(mxb, __shfl_xor_sync(0xffffffffu, mxb, 1));
    mxb = fmaxf(mxb, __shfl_xor_sync(0xffffffffu, mxb, 2));

    float suma = 0.f, sumb = 0.f;
    #pragma unroll
    for (int i = 0; i < 16; i++) {
        sa[i] = __expf(sa[i] - mxa); suma += sa[i];
        sb[i] = __expf(sb[i] - mxb); sumb += sb[i];
    }
    suma += __shfl_xor_sync(0xffffffffu, suma, 1);
    suma += __shfl_xor_sync(0xffffffffu, suma, 2);
    sumb += __shfl_xor_sync(0xffffffffu, sumb, 1);
    sumb += __shfl_xor_sync(0xffffffffu, sumb, 2);
    const float inva = 1.f / suma, invb = 1.f / sumb;

    #pragma unroll
    for (int j = 0; j < 8; j++) {
        float wa0 = sa[2*j]   * inva - 0.015625f;   // exact (Sterbenz)
        float wa1 = sa[2*j+1] * inva - 0.015625f;
        float wb0 = sb[2*j]   * invb - 0.015625f;
        float wb1 = sb[2*j+1] * invb - 0.015625f;
        __nv_bfloat162 ha = __floats2bfloat162_rn(wa0, wa1);
        __nv_bfloat162 hb = __floats2bfloat162_rn(wb0, wb1);
        *(__nv_bfloat162*)(g_wres + (size_t)(r0 + raL) * E_ + 8 * j + tc) = ha;
        *(__nv_bfloat162*)(g_wres + (size_t)(r0 + rbL) * E_ + 8 * j + tc) = hb;
    }
}

// ---------------------------------------------------------------------------
// k4: out_w = mean + wres @ ek via mma.sync bf16. grid (B/128, D/64).
// CTA: 128m x 64d, K = E = 64.
// ---------------------------------------------------------------------------
__global__ __launch_bounds__(256) void k4_mma(float* __restrict__ out_w) {
    __shared__ __align__(16) __nv_bfloat16 sA[128 * PAD];
    __shared__ __align__(16) __nv_bfloat16 sB[64 * PAD];

    const int tid = threadIdx.x;
    const int wid = tid >> 5, lane = tid & 31;
    const int r0 = blockIdx.x * 128;
    const int dc = blockIdx.y * 64;

    {   // stage A: wres 128 rows x 8 uint4 (2 threads/row, 4 each)
        int r = tid >> 1, half = tid & 1;
        const __nv_bfloat16* src = g_wres + (size_t)(r0 + r) * E_;
        #pragma unroll
        for (int u = 0; u < 4; u++) {
            int c16 = half * 4 + u;
            uint4 v = *(const uint4*)(src + c16 * 8);
            *(uint4*)(sA + r * PAD + c16 * 8) = v;
        }
    }
    {   // stage B: ekT rows dc..dc+63 (4 threads/row, 2 each)
        int r = tid >> 2, q = tid & 3;
        const __nv_bfloat16* src = g_ekTb + (size_t)(dc + r) * E_;
        #pragma unroll
        for (int u = 0; u < 2; u++) {
            int c16 = q * 2 + u;
            uint4 v = *(const uint4*)(src + c16 * 8);
            *(uint4*)(sB + r * PAD + c16 * 8) = v;
        }
    }
    __syncthreads();

    const unsigned sA_addr = (unsigned)__cvta_generic_to_shared(sA);
    const unsigned sB_addr = (unsigned)__cvta_generic_to_shared(sB);
    const int l7 = lane & 7;
    const int aRow = wid * 16 + l7 + ((lane >> 3) & 1) * 8;
    const int aKo  = (lane >> 4) * 8;
    const int bNo  = l7 + (lane >> 4) * 8;
    const int bKo  = ((lane >> 3) & 1) * 8;

    float c[8][4];
    #pragma unroll
    for (int j = 0; j < 8; j++)
        #pragma unroll
        for (int q = 0; q < 4; q++) c[j][q] = 0.f;

    #pragma unroll
    for (int k16 = 0; k16 < 4; k16++) {
        const int k0 = k16 * 16;
        unsigned a0, a1, a2, a3;
        ldsm_x4(a0, a1, a2, a3, sA_addr + (aRow * PAD + k0 + aKo) * 2);
        #pragma unroll
        for (int g = 0; g < 4; g++) {
            unsigned b0, b1, b2, b3;
            ldsm_x4(b0, b1, b2, b3,
                    sB_addr + ((16 * g + bNo) * PAD + k0 + bKo) * 2);
            mma_bf16(c[2*g][0], c[2*g][1], c[2*g][2], c[2*g][3],
                     a0, a1, a2, a3, b0, b1);
            mma_bf16(c[2*g+1][0], c[2*g+1][1], c[2*g+1][2], c[2*g+1][3],
                     a0, a1, a2, a3, b2, b3);
        }
    }

    const int gr = lane >> 2, tc = (lane & 3) * 2;
    const int mrow = r0 + wid * 16 + gr;
    #pragma unroll
    for (int j = 0; j < 8; j++) {
        float2 mn = *(const float2*)(g_mean + dc + 8 * j + tc);
        *(float2*)(out_w + (size_t)mrow * D_ + dc + 8 * j + tc)
            = make_float2(c[j][0] + mn.x, c[j][1] + mn.y);
        *(float2*)(out_w + (size_t)(mrow + 8) * D_ + dc + 8 * j + tc)
            = make_float2(c[j][2] + mn.x, c[j][3] + mn.y);
    }
}

// ---------------------------------------------------------------------------
extern "C" void kernel_launch(void* const* d_in, const int* in_sizes, int n_in,
                              void* d_out, int out_size) {
    const float* z  = (const float*)d_in[0];   // [B, D]
    const float* ek = (const float*)d_in[1];   // [E, D]
    const float* ls = (const float*)d_in[2];   // [D]
    float* out = (float*)d_out;
    float* out_sim = out;                      // [B, E]
    float* out_w   = out + (size_t)B_ * E_;    // [B, D]

    prep_kernel<<<E_, 256>>>(ek, ls);
    meank<<<D_ / 256, 256>>>(ek);
    kA_dist<<<B_ / 64, 128>>>(z, out_sim);
    k4_mma<<<dim3(B_ / 128, D_ / 64), 256>>>(out_w);
}

// round 15
// speedup vs baseline: 1.4319x; 1.4319x over previous
#include <cuda_runtime.h>
#include <cuda_bf16.h>
#include <math.h>

#define B_     4096
#define E_     64
#define D_     1024
#define KSPLIT 4
#define KCTA   (D_ / KSPLIT)   // 256 k per CTA
#define BKC    64              // k per chunk

// ---------------- scratch (__device__ globals; no allocs allowed) ----------
__device__ __align__(16) float         g_sinv[D_];
__device__ __align__(16) __nv_bfloat16 g_esb[E_ * D_];    // bf16 sinv*ek, [e][d]
__device__ __align__(16) __nv_bfloat16 g_ekTb[D_ * E_];   // bf16 ek^T, [d][e]
__device__ __align__(16) __nv_bfloat16 g_wres[B_ * E_];   // bf16 (w - 1/64)
__device__ __align__(16) float         g_en[E_];
__device__ __align__(16) float         g_mean[D_];        // (1/64)*colsum(ek)
__device__ __align__(16) float         g_part[KSPLIT * B_ * E_];  // 4 MB
__device__ __align__(16) float         g_znp[KSPLIT * B_];

// ---------------- mma.sync helpers (base ISA, compute_103-safe) ------------
static __device__ __forceinline__ void ldsm_x4(unsigned& r0, unsigned& r1,
                                               unsigned& r2, unsigned& r3,
                                               unsigned addr) {
    asm volatile("ldmatrix.sync.aligned.m8n8.x4.shared.b16 {%0,%1,%2,%3}, [%4];"
                 : "=r"(r0), "=r"(r1), "=r"(r2), "=r"(r3) : "r"(addr));
}
static __device__ __forceinline__ void mma_bf16(float& c0, float& c1,
                                                float& c2, float& c3,
                                                unsigned a0, unsigned a1,
                                                unsigned a2, unsigned a3,
                                                unsigned b0, unsigned b1) {
    asm volatile(
        "mma.sync.aligned.m16n8k16.row.col.f32.bf16.bf16.f32 "
        "{%0,%1,%2,%3}, {%4,%5,%6,%7}, {%8,%9}, {%0,%1,%2,%3};"
        : "+f"(c0), "+f"(c1), "+f"(c2), "+f"(c3)
        : "r"(a0), "r"(a1), "r"(a2), "r"(a3), "r"(b0), "r"(b1));
}

#define PAD 72   // 144 B row stride -> 4-bank skew, conflict-free ldmatrix

// ---------------------------------------------------------------------------
// prep (+fused meank): blocks 0-63 per-expert prep; blocks 64-67 column mean.
// ---------------------------------------------------------------------------
__global__ __launch_bounds__(256) void prep_kernel(const float* __restrict__ ek,
                                                   const float* __restrict__ ls) {
    int tid = threadIdx.x;
    if (blockIdx.x >= E_) {
        int d = (blockIdx.x - E_) * 256 + tid;
        float acc = 0.f;
        #pragma unroll 8
        for (int e = 0; e < E_; e++) acc += ek[(size_t)e * D_ + d];
        g_mean[d] = acc * 0.015625f;
        return;
    }
    int e = blockIdx.x;
    float acc = 0.f;
    for (int d = tid; d < D_; d += 256) {
        float s = __expf(-ls[d]);
        if (e == 0) g_sinv[d] = s;
        float v = ek[e * D_ + d];
        float sv = s * v;
        g_esb[e * D_ + d] = __float2bfloat16(sv);
        g_ekTb[d * E_ + e] = __float2bfloat16(v);
        acc += sv * v;
    }
    __shared__ float red[8];
    #pragma unroll
    for (int o = 16; o > 0; o >>= 1) acc += __shfl_down_sync(0xffffffffu, acc, o);
    if ((tid & 31) == 0) red[tid >> 5] = acc;
    __syncthreads();
    if (tid == 0) {
        float s = 0.f;
        #pragma unroll
        for (int i = 0; i < 8; i++) s += red[i];
        g_en[e] = s;
    }
}

// ---------------------------------------------------------------------------
// k2: dist partial GEMM, fp32 z read + inline bf16 convert + zn partials.
// grid (B/128, KSPLIT) = (32,4) = 128 CTAs, 256 threads (8 warps, 2 CTAs/SM).
// CTA: 128m x 64e x 256k (4 chunks of 64, reg prefetch, single smem buffer).
// smem: sA 18432 + sB 9216 + s_sinv 1024 = 28.7 KB.
// ---------------------------------------------------------------------------
__global__ __launch_bounds__(256) void k2_mma(const float* __restrict__ z) {
    __shared__ __align__(16) __nv_bfloat16 sA[128 * PAD];
    __shared__ __align__(16) __nv_bfloat16 sB[64 * PAD];
    __shared__ __align__(16) float s_sinv[KCTA];

    const int tid = threadIdx.x;
    const int wid = tid >> 5, lane = tid & 31;
    const int r0 = blockIdx.x * 128;
    const int ks = blockIdx.y;
    const int kbase = ks * KCTA;

    for (int i = tid; i < KCTA / 4; i += 256)
        ((float4*)s_sinv)[i] = ((const float4*)(g_sinv + kbase))[i];

    // staging roles
    const int ra = tid >> 1, h = tid & 1;         // A: 2 thr/row, 32 floats each
    const int rb = tid >> 2, q = tid & 3;         // B: 4 thr/row, 16 bf16 each
    const float* zrow = z + (size_t)(r0 + ra) * D_ + kbase + h * 32;
    const __nv_bfloat16* erow = g_esb + (size_t)rb * D_ + kbase + q * 16;

    float4 za[8];
    uint4  eb[2];
    {   // prefetch chunk 0
        const float4* zs = (const float4*)zrow;
        #pragma unroll
        for (int u = 0; u < 8; u++) za[u] = zs[u];
        const uint4* es = (const uint4*)erow;
        eb[0] = es[0]; eb[1] = es[1];
    }

    const int l7 = lane & 7;
    const int aRow = wid * 16 + l7 + ((lane >> 3) & 1) * 8;
    const int aKo  = (lane >> 4) * 8;
    const int bNo  = l7 + (lane >> 4) * 8;
    const int bKo  = ((lane >> 3) & 1) * 8;
    const unsigned sA_addr = (unsigned)__cvta_generic_to_shared(sA);
    const unsigned sB_addr = (unsigned)__cvta_generic_to_shared(sB);

    float acc[8][4];
    #pragma unroll
    for (int j = 0; j < 8; j++)
        #pragma unroll
        for (int t = 0; t < 4; t++) acc[j][t] = 0.f;
    float zn = 0.f;

    for (int c = 0; c < KCTA / BKC; c++) {
        if (c) __syncthreads();          // all warps done reading smem chunk c-1
        {   // store regs -> smem (convert + zn accumulate)
            const float* sv = s_sinv + c * 64 + h * 32;
            #pragma unroll
            for (int u = 0; u < 8; u++) {
                float4 f = za[u];
                float4 s = *(const float4*)(sv + 4 * u);
                zn += s.x * f.x * f.x + s.y * f.y * f.y
                    + s.z * f.z * f.z + s.w * f.w * f.w;
                __nv_bfloat162 b01 = __floats2bfloat162_rn(f.x, f.y);
                __nv_bfloat162 b23 = __floats2bfloat162_rn(f.z, f.w);
                uint2 pk;
                pk.x = *reinterpret_cast<unsigned*>(&b01);
                pk.y = *reinterpret_cast<unsigned*>(&b23);
                *(uint2*)(&sA[ra * PAD + h * 32 + 4 * u]) = pk;
            }
            *(uint4*)(&sB[rb * PAD + q * 16])     = eb[0];
            *(uint4*)(&sB[rb * PAD + q * 16 + 8]) = eb[1];
        }
        __syncthreads();
        if (c < KCTA / BKC - 1) {   // prefetch next chunk (overlaps MMA)
            const float4* zs = (const float4*)(zrow + (c + 1) * 64);
            #pragma unroll
            for (int u = 0; u < 8; u++) za[u] = zs[u];
            const uint4* es = (const uint4*)(erow + (c + 1) * 64);
            eb[0] = es[0]; eb[1] = es[1];
        }
        #pragma unroll
        for (int k16 = 0; k16 < 4; k16++) {
            const int k0 = k16 * 16;
            unsigned a0, a1, a2, a3;
            ldsm_x4(a0, a1, a2, a3, sA_addr + (aRow * PAD + k0 + aKo) * 2);
            #pragma unroll
            for (int g = 0; g < 4; g++) {
                unsigned b0, b1, b2, b3;
                ldsm_x4(b0, b1, b2, b3,
                        sB_addr + ((16 * g + bNo) * PAD + k0 + bKo) * 2);
                mma_bf16(acc[2*g][0], acc[2*g][1], acc[2*g][2], acc[2*g][3],
                         a0, a1, a2, a3, b0, b1);
                mma_bf16(acc[2*g+1][0], acc[2*g+1][1], acc[2*g+1][2], acc[2*g+1][3],
                         a0, a1, a2, a3, b2, b3);
            }
        }
    }

    // zn partial (2 adjacent lanes per row)
    zn += __shfl_xor_sync(0xffffffffu, zn, 1);
    if (h == 0) g_znp[ks * B_ + r0 + ra] = zn;

    // epilogue: partial dots -> g_part
    const int gr = lane >> 2, tc = (lane & 3) * 2;
    const int mrow = r0 + wid * 16 + gr;
    float* dst = g_part + ((size_t)ks * B_ + mrow) * E_;
    #pragma unroll
    for (int j = 0; j < 8; j++) {
        *(float2*)(dst + 8 * j + tc)          = make_float2(acc[j][0], acc[j][1]);
        *(float2*)(dst + 8 * E_ + 8 * j + tc) = make_float2(acc[j][2], acc[j][3]);
    }
}

// ---------------------------------------------------------------------------
// k3: reduce partials + zn + similarity + softmax + residual weights
// ---------------------------------------------------------------------------
__global__ __launch_bounds__(256) void k3_softmax(float* __restrict__ out_sim) {
    const int lane = threadIdx.x & 31;
    const int m = blockIdx.x * 8 + (threadIdx.x >> 5);

    float dx = 0.f, dy = 0.f, zn = 0.f;
    #pragma unroll
    for (int ksp = 0; ksp < KSPLIT; ksp++) {
        float2 pp = *(const float2*)(g_part + ((size_t)ksp * B_ + m) * E_ + 2 * lane);
        dx += pp.x; dy += pp.y;
        zn += g_znp[ksp * B_ + m];
    }
    float2 en = *(const float2*)(g_en + 2 * lane);
    float sim0 = 1.f / (1.f + zn + en.x - 2.f * dx);
    float sim1 = 1.f / (1.f + zn + en.y - 2.f * dy);
    *(float2*)(out_sim + (size_t)m * E_ + 2 * lane) = make_float2(sim0, sim1);

    float mx = fmaxf(sim0, sim1);
    #pragma unroll
    for (int o = 16; o; o >>= 1) mx = fmaxf(mx, __shfl_xor_sync(0xffffffffu, mx, o));
    float e0 = __expf(sim0 - mx), e1 = __expf(sim1 - mx);
    float s = e0 + e1;
    #pragma unroll
    for (int o = 16; o; o >>= 1) s += __shfl_xor_sync(0xffffffffu, s, o);
    float inv = 1.f / s;
    float w0 = e0 * inv - 0.015625f;   // exact (Sterbenz)
    float w1 = e1 * inv - 0.015625f;
    __nv_bfloat162 hh = __floats2bfloat162_rn(w0, w1);
    *(__nv_bfloat162*)(g_wres + (size_t)m * E_ + 2 * lane) = hh;
}

// ---------------------------------------------------------------------------
// k4: out_w = mean + wres @ ek. grid (B/128, D/256) = (32,4) = 128 CTAs.
// CTA: 128m x 256d (4 d-tiles), K=E=64. wres staged ONCE; ek tiles reg-prefetched.
// smem: sA 18432 + sB 9216 = 27.6 KB.
// ---------------------------------------------------------------------------
__global__ __launch_bounds__(256) void k4_mma(float* __restrict__ out_w) {
    __shared__ __align__(16) __nv_bfloat16 sA[128 * PAD];
    __shared__ __align__(16) __nv_bfloat16 sB[64 * PAD];

    const int tid = threadIdx.x;
    const int wid = tid >> 5, lane = tid & 31;
    const int r0 = blockIdx.x * 128;
    const int dc0 = blockIdx.y * 256;

    // stage A (wres 128x64) + B tile 0 directly
    {
        int r = tid >> 1, half = tid & 1;
        const __nv_bfloat16* src = g_wres + (size_t)(r0 + r) * E_;
        #pragma unroll
        for (int u = 0; u < 4; u++) {
            int c16 = half * 4 + u;
            uint4 v = *(const uint4*)(src + c16 * 8);
            *(uint4*)(&sA[r * PAD + c16 * 8]) = v;
        }
    }
    const int rb = tid >> 2, q = tid & 3;
    const __nv_bfloat16* brow = g_ekTb + (size_t)(dc0 + rb) * E_ + q * 16;
    {
        const uint4* es = (const uint4*)brow;
        uint4 v0 = es[0], v1 = es[1];
        *(uint4*)(&sB[rb * PAD + q * 16])     = v0;
        *(uint4*)(&sB[rb * PAD + q * 16 + 8]) = v1;
    }
    __syncthreads();

    const unsigned sA_addr = (unsigned)__cvta_generic_to_shared(sA);
    const unsigned sB_addr = (unsigned)__cvta_generic_to_shared(sB);
    const int l7 = lane & 7;
    const int aRow = wid * 16 + l7 + ((lane >> 3) & 1) * 8;
    const int aKo  = (lane >> 4) * 8;
    const int bNo  = l7 + (lane >> 4) * 8;
    const int bKo  = ((lane >> 3) & 1) * 8;
    const int gr = lane >> 2, tc = (lane & 3) * 2;
    const int mrow = r0 + wid * 16 + gr;

    uint4 eb[2];
    for (int dt = 0; dt < 4; dt++) {
        if (dt) {
            __syncthreads();   // all warps done reading previous sB
            *(uint4*)(&sB[rb * PAD + q * 16])     = eb[0];
            *(uint4*)(&sB[rb * PAD + q * 16 + 8]) = eb[1];
            __syncthreads();
        }
        if (dt < 3) {   // prefetch next ek tile (64 rows down in ekT)
            const uint4* es = (const uint4*)(brow + (size_t)(dt + 1) * 64 * E_);
            eb[0] = es[0]; eb[1] = es[1];
        }

        float c[8][4];
        #pragma unroll
        for (int j = 0; j < 8; j++)
            #pragma unroll
            for (int t = 0; t < 4; t++) c[j][t] = 0.f;

        #pragma unroll
        for (int k16 = 0; k16 < 4; k16++) {
            const int k0 = k16 * 16;
            unsigned a0, a1, a2, a3;
            ldsm_x4(a0, a1, a2, a3, sA_addr + (aRow * PAD + k0 + aKo) * 2);
            #pragma unroll
            for (int g = 0; g < 4; g++) {
                unsigned b0, b1, b2, b3;
                ldsm_x4(b0, b1, b2, b3,
                        sB_addr + ((16 * g + bNo) * PAD + k0 + bKo) * 2);
                mma_bf16(c[2*g][0], c[2*g][1], c[2*g][2], c[2*g][3],
                         a0, a1, a2, a3, b0, b1);
                mma_bf16(c[2*g+1][0], c[2*g+1][1], c[2*g+1][2], c[2*g+1][3],
                         a0, a1, a2, a3, b2, b3);
            }
        }

        const int dc = dc0 + dt * 64;
        #pragma unroll
        for (int j = 0; j < 8; j++) {
            float2 mn = *(const float2*)(g_mean + dc + 8 * j + tc);
            *(float2*)(out_w + (size_t)mrow * D_ + dc + 8 * j + tc)
                = make_float2(c[j][0] + mn.x, c[j][1] + mn.y);
            *(float2*)(out_w + (size_t)(mrow + 8) * D_ + dc + 8 * j + tc)
                = make_float2(c[j][2] + mn.x, c[j][3] + mn.y);
        }
    }
}

// ---------------------------------------------------------------------------
extern "C" void kernel_launch(void* const* d_in, const int* in_sizes, int n_in,
                              void* d_out, int out_size) {
    const float* z  = (const float*)d_in[0];   // [B, D]
    const float* ek = (const float*)d_in[1];   // [E, D]
    const float* ls = (const float*)d_in[2];   // [D]
    float* out = (float*)d_out;
    float* out_sim = out;                      // [B, E]
    float* out_w   = out + (size_t)B_ * E_;    // [B, D]

    prep_kernel<<<E_ + D_ / 256, 256>>>(ek, ls);
    k2_mma<<<dim3(B_ / 128, KSPLIT), 256>>>(z);
    k3_softmax<<<B_ / 8, 256>>>(out_sim);
    k4_mma<<<dim3(B_ / 128, D_ / 256), 256>>>(out_w);
}